// round 4
// baseline (speedup 1.0000x reference)
#include <cuda_runtime.h>
#include <cstdio>

#define SEQ      2048
#define BSZ      2
#define DIM      768
#define NH       12
#define HD       64
#define QKV_N    (3*DIM)      // 2304
#define M_ROWS   (BSZ*SEQ)    // 4096

typedef unsigned long long ull;

// ---------------- packed f32x2 helpers (sm_103a FFMA2) ----------------
__device__ __forceinline__ ull pack2(float x, float y) {
    ull r; asm("mov.b64 %0, {%1, %2};" : "=l"(r) : "f"(x), "f"(y)); return r;
}
__device__ __forceinline__ ull ffma2(ull a, ull b, ull c) {
    ull d; asm("fma.rn.f32x2 %0, %1, %2, %3;" : "=l"(d) : "l"(a), "l"(b), "l"(c)); return d;
}
__device__ __forceinline__ ull fmul2(ull a, ull b) {
    ull d; asm("mul.rn.f32x2 %0, %1, %2;" : "=l"(d) : "l"(a), "l"(b)); return d;
}
__device__ __forceinline__ float2 unpack2(ull v) {
    float2 f; asm("mov.b64 {%0, %1}, %2;" : "=f"(f.x), "=f"(f.y) : "l"(v)); return f;
}

// ---------------- scratch (static device globals; no allocation) ----------------
__device__ float g_qkv[(size_t)M_ROWS * QKV_N];   // [b*s, 2304]
__device__ float g_att[(size_t)M_ROWS * DIM];     // [b*s, 768]

// ---------------- SGEMM with bias, f32x2 inner product ----------------
#define BM 128
#define BN 128
#define BK 16

__global__ __launch_bounds__(256)
void sgemm_bias(const float* __restrict__ A, const float* __restrict__ B,
                const float* __restrict__ bias, float* __restrict__ C,
                int M, int N, int K)
{
    __shared__ __align__(16) float As[BK][BM + 4];
    __shared__ __align__(16) float Bs[BK][BN];

    const int tid = threadIdx.x;
    const int bx = blockIdx.x;
    const int by = blockIdx.y;

    const int tx = tid & 15;
    const int ty = tid >> 4;

    ull acc2[8][4];
    #pragma unroll
    for (int i = 0; i < 8; i++)
        #pragma unroll
        for (int j = 0; j < 4; j++) acc2[i][j] = 0ull;   // two packed +0.0f

    const int a_row = tid >> 2;
    const int a_col = (tid & 3) * 4;
    const int b_row = tid >> 5;
    const int b_col = (tid & 31) * 4;

    const float* Ab = A + (size_t)(by * BM) * K;
    const float* Bb = B + (size_t)(bx * BN);

    for (int k0 = 0; k0 < K; k0 += BK) {
        #pragma unroll
        for (int i = 0; i < 2; i++) {
            int r = a_row + i * 64;
            float4 v = *(const float4*)(Ab + (size_t)r * K + k0 + a_col);
            As[a_col + 0][r] = v.x;
            As[a_col + 1][r] = v.y;
            As[a_col + 2][r] = v.z;
            As[a_col + 3][r] = v.w;
        }
        #pragma unroll
        for (int i = 0; i < 2; i++) {
            int r = b_row + i * 8;
            float4 v = *(const float4*)(Bb + (size_t)(k0 + r) * N + b_col);
            *(float4*)(&Bs[r][b_col]) = v;
        }
        __syncthreads();

        #pragma unroll
        for (int kk = 0; kk < BK; kk++) {
            ull b2[4];
            #pragma unroll
            for (int j = 0; j < 4; j++)
                b2[j] = *(const ull*)(&Bs[kk][tx * 8 + 2 * j]);
            #pragma unroll
            for (int i = 0; i < 8; i++) {
                float a = As[kk][ty * 8 + i];
                ull a2 = pack2(a, a);
                #pragma unroll
                for (int j = 0; j < 4; j++)
                    acc2[i][j] = ffma2(a2, b2[j], acc2[i][j]);
            }
        }
        __syncthreads();
    }

    #pragma unroll
    for (int i = 0; i < 8; i++) {
        const int row = by * BM + ty * 8 + i;
        const int col = bx * BN + tx * 8;
        float2 f0 = unpack2(acc2[i][0]);
        float2 f1 = unpack2(acc2[i][1]);
        float2 f2 = unpack2(acc2[i][2]);
        float2 f3 = unpack2(acc2[i][3]);
        float4 v0, v1;
        v0.x = f0.x + bias[col + 0];
        v0.y = f0.y + bias[col + 1];
        v0.z = f1.x + bias[col + 2];
        v0.w = f1.y + bias[col + 3];
        v1.x = f2.x + bias[col + 4];
        v1.y = f2.y + bias[col + 5];
        v1.z = f3.x + bias[col + 6];
        v1.w = f3.y + bias[col + 7];
        *(float4*)(C + (size_t)row * N + col)     = v0;
        *(float4*)(C + (size_t)row * N + col + 4) = v1;
    }
}

// ---------------- flash-style causal attention, 4 lanes per query, f32x2 ----------------
// grid (32 q-tiles, 12 heads, 2 batch), 256 threads.
// Lane group of 4 owns one query row; lane `part` owns dim-pairs {part+4i : i=0..7}
// (interleaved so the 4 lanes hit 4 distinct smem banks -> conflict-free broadcast).
#define QT 64
#define KT 32

__global__ __launch_bounds__(256)
void attn_kernel(const float* __restrict__ qkv, float* __restrict__ att)
{
    const int qt = blockIdx.x;
    const int h  = blockIdx.y;
    const int b  = blockIdx.z;
    const int t  = threadIdx.x;
    const int ql   = t >> 2;          // query within tile (0..63)
    const int part = t & 3;           // dim partition (0..3)
    const int qi = qt * QT + ql;

    __shared__ __align__(16) float sK[KT][HD];
    __shared__ __align__(16) float sV[KT][HD];

    const float scale = 0.125f;       // 1/sqrt(64)

    const float* qrow = qkv + ((size_t)(b * SEQ + qi)) * QKV_N + h * HD;
    ull q2[8], o2[8];
    #pragma unroll
    for (int i = 0; i < 8; i++) {
        int d = 2 * (part + 4 * i);
        q2[i] = pack2(qrow[d] * scale, qrow[d + 1] * scale);
        o2[i] = 0ull;
    }

    float m = -1e30f, l = 0.f;
    const int ntiles = qt * 2 + 2;    // keys [0, (qt+1)*64) in 32-row tiles

    for (int kt = 0; kt < ntiles; kt++) {
        const int s0 = kt * KT;
        const float* kbase = qkv + ((size_t)(b * SEQ + s0)) * QKV_N + DIM + h * HD;
        const float* vbase = kbase + DIM;

        // cooperative tile load: 512 float4 per matrix / 256 threads = 2 each
        #pragma unroll
        for (int i = t; i < KT * HD / 4; i += 256) {
            int r = i >> 4;
            int c = (i & 15) * 4;
            *(float4*)(&sK[r][c]) = *(const float4*)(kbase + (size_t)r * QKV_N + c);
            *(float4*)(&sV[r][c]) = *(const float4*)(vbase + (size_t)r * QKV_N + c);
        }
        __syncthreads();

        float sv[KT];
        float smax = -1e30f;
        #pragma unroll
        for (int j = 0; j < KT; j++) {
            ull acc = 0ull;
            #pragma unroll
            for (int i = 0; i < 8; i++)
                acc = ffma2(q2[i], *(const ull*)(&sK[j][2 * (part + 4 * i)]), acc);
            float2 f = unpack2(acc);
            float s = f.x + f.y;
            s += __shfl_xor_sync(0xffffffffu, s, 1);
            s += __shfl_xor_sync(0xffffffffu, s, 2);
            if (s0 + j > qi) s = -1e30f;     // causal mask
            sv[j] = s;
            smax = fmaxf(smax, s);
        }

        const float mnew = fmaxf(m, smax);
        const float corr = __expf(m - mnew);
        l *= corr;
        const ull corr2 = pack2(corr, corr);
        #pragma unroll
        for (int i = 0; i < 8; i++) o2[i] = fmul2(o2[i], corr2);

        #pragma unroll
        for (int j = 0; j < KT; j++) {
            float p = __expf(sv[j] - mnew);
            l += p;
            ull p2 = pack2(p, p);
            #pragma unroll
            for (int i = 0; i < 8; i++)
                o2[i] = ffma2(p2, *(const ull*)(&sV[j][2 * (part + 4 * i)]), o2[i]);
        }
        m = mnew;
        __syncthreads();
    }

    const float inv = 1.f / l;
    float* orow = att + ((size_t)(b * SEQ + qi)) * DIM + h * HD;
    #pragma unroll
    for (int i = 0; i < 8; i++) {
        float2 f = unpack2(o2[i]);
        int d = 2 * (part + 4 * i);
        float2 w; w.x = f.x * inv; w.y = f.y * inv;
        *(float2*)(orow + d) = w;
    }
}

// ---------------- launch ----------------
extern "C" void kernel_launch(void* const* d_in, const int* in_sizes, int n_in,
                              void* d_out, int out_size)
{
    const float* x     = (const float*)d_in[0];
    const float* Wqkv  = (const float*)d_in[1];
    const float* bqkv  = (const float*)d_in[2];
    const float* Wproj = (const float*)d_in[3];
    const float* bproj = (const float*)d_in[4];
    float* out = (float*)d_out;

    float* qkv = nullptr;
    float* att = nullptr;
    cudaGetSymbolAddress((void**)&qkv, g_qkv);
    cudaGetSymbolAddress((void**)&att, g_att);

    dim3 g1(QKV_N / BN, M_ROWS / BM);
    sgemm_bias<<<g1, 256>>>(x, Wqkv, bqkv, qkv, M_ROWS, QKV_N, DIM);

    dim3 g2(SEQ / QT, NH, BSZ);
    attn_kernel<<<g2, 256>>>(qkv, att);

    dim3 g3(DIM / BN, M_ROWS / BM);
    sgemm_bias<<<g3, 256>>>(att, Wproj, bproj, out, M_ROWS, DIM, DIM);
}

// round 5
// speedup vs baseline: 1.5565x; 1.5565x over previous
#include <cuda_runtime.h>
#include <cstdio>

#define SEQ      2048
#define BSZ      2
#define DIM      768
#define NH       12
#define HD       64
#define QKV_N    (3*DIM)      // 2304
#define M_ROWS   (BSZ*SEQ)    // 4096

// ---------------- scratch (static device globals; no allocation) ----------------
__device__ float g_qkv[(size_t)M_ROWS * QKV_N];   // [b*s, 2304]
__device__ float g_att[(size_t)M_ROWS * DIM];     // [b*s, 768]

// ---------------- SGEMM with bias (conflict-free b reads: col = tx + 16j) ----------------
#define BM 128
#define BN 128
#define BK 16

__global__ __launch_bounds__(256)
void sgemm_bias(const float* __restrict__ A, const float* __restrict__ B,
                const float* __restrict__ bias, float* __restrict__ C,
                int M, int N, int K)
{
    __shared__ __align__(16) float As[BK][BM + 4];
    __shared__ __align__(16) float Bs[BK][BN];

    const int tid = threadIdx.x;
    const int bx = blockIdx.x;
    const int by = blockIdx.y;

    const int tx = tid & 15;
    const int ty = tid >> 4;

    float acc[8][8];
    #pragma unroll
    for (int i = 0; i < 8; i++)
        #pragma unroll
        for (int j = 0; j < 8; j++) acc[i][j] = 0.f;

    const int a_row = tid >> 2;
    const int a_col = (tid & 3) * 4;
    const int b_row = tid >> 5;
    const int b_col = (tid & 31) * 4;

    const float* Ab = A + (size_t)(by * BM) * K;
    const float* Bb = B + (size_t)(bx * BN);

    for (int k0 = 0; k0 < K; k0 += BK) {
        #pragma unroll
        for (int i = 0; i < 2; i++) {
            int r = a_row + i * 64;
            float4 v = *(const float4*)(Ab + (size_t)r * K + k0 + a_col);
            As[a_col + 0][r] = v.x;
            As[a_col + 1][r] = v.y;
            As[a_col + 2][r] = v.z;
            As[a_col + 3][r] = v.w;
        }
        #pragma unroll
        for (int i = 0; i < 2; i++) {
            int r = b_row + i * 8;
            float4 v = *(const float4*)(Bb + (size_t)(k0 + r) * N + b_col);
            *(float4*)(&Bs[r][b_col]) = v;
        }
        __syncthreads();

        #pragma unroll
        for (int kk = 0; kk < BK; kk++) {
            float a[8], b[8];
            #pragma unroll
            for (int i = 0; i < 8; i++) a[i] = As[kk][ty * 8 + i];
            #pragma unroll
            for (int j = 0; j < 8; j++) b[j] = Bs[kk][tx + 16 * j];   // 16 lanes -> 16 banks
            #pragma unroll
            for (int i = 0; i < 8; i++)
                #pragma unroll
                for (int j = 0; j < 8; j++)
                    acc[i][j] += a[i] * b[j];
        }
        __syncthreads();
    }

    #pragma unroll
    for (int i = 0; i < 8; i++) {
        const int row = by * BM + ty * 8 + i;
        #pragma unroll
        for (int j = 0; j < 8; j++) {
            const int col = bx * BN + tx + 16 * j;
            C[(size_t)row * N + col] = acc[i][j] + bias[col];
        }
    }
}

// ---------------- flash attention v3: 128x128 tiles, GEMM-style register blocking ----------------
// Block: 256 threads handle QT=128 queries of one (b,h). K tiles of KT=128.
// Phase A: S(128x128) = Q @ K^T, 8x8 per thread, Q/K d-major in smem (conflict-free).
// Phase B: O(128x64) += P @ V, 8q x 4d per thread, P in smem.
#define QT 128
#define KTILE 128

#define SQ_STRIDE 132
#define SP_STRIDE 130

// smem float offsets
#define OFF_Q  0
#define OFF_K  (64 * SQ_STRIDE)                 // 8448
#define OFF_V  (OFF_K + 64 * SQ_STRIDE)         // 16896
#define OFF_P  (OFF_V + 128 * 64)               // 25088
#define OFF_M  (OFF_P + 128 * SP_STRIDE)        // 41728
#define OFF_L  (OFF_M + 128)
#define OFF_C  (OFF_L + 128)
#define SMEM_FLOATS (OFF_C + 128)               // 42240 floats = 168960 B

__global__ __launch_bounds__(256, 1)
void attn_kernel(const float* __restrict__ qkv, float* __restrict__ att)
{
    extern __shared__ float sm[];
    float* sQ = sm + OFF_Q;    // [64][132] d-major
    float* sK = sm + OFF_K;    // [64][132] d-major
    float* sV = sm + OFF_V;    // [128][64] k-major
    float* sP = sm + OFF_P;    // [128][130]
    float* sM = sm + OFF_M;
    float* sL = sm + OFF_L;
    float* sCorr = sm + OFF_C;

    const int qt = (gridDim.x - 1) - blockIdx.x;   // heavy blocks first
    const int h  = blockIdx.y;
    const int b  = blockIdx.z;
    const int tid = threadIdx.x;
    const int ty = tid >> 4;    // 0..15 : q-row group
    const int tk = tid & 15;    // 0..15 : k-col lane
    const int qbase = qt * QT;

    const float scale = 0.125f;   // 1/sqrt(64)

    // ---- load Q tile transposed (d-major), scale folded ----
    {
        const float* qb = qkv + ((size_t)(b * SEQ + qbase)) * QKV_N + h * HD;
        #pragma unroll
        for (int i = tid; i < 2048; i += 256) {
            int r = i & 127;
            int dq = (i >> 7) * 4;
            float4 v = *(const float4*)(qb + (size_t)r * QKV_N + dq);
            sQ[(dq + 0) * SQ_STRIDE + r] = v.x * scale;
            sQ[(dq + 1) * SQ_STRIDE + r] = v.y * scale;
            sQ[(dq + 2) * SQ_STRIDE + r] = v.z * scale;
            sQ[(dq + 3) * SQ_STRIDE + r] = v.w * scale;
        }
    }
    if (tid < 128) { sM[tid] = -1e30f; sL[tid] = 0.f; }

    // persistent O accumulators: rows ty*8+i, dims tk*4+j  (phase-B mapping == (ty,tk))
    float o_acc[8][4];
    #pragma unroll
    for (int i = 0; i < 8; i++)
        #pragma unroll
        for (int j = 0; j < 4; j++) o_acc[i][j] = 0.f;

    const int ntiles = qt + 1;

    for (int kt = 0; kt < ntiles; kt++) {
        const int s0 = kt * KTILE;
        const float* kb = qkv + ((size_t)(b * SEQ + s0)) * QKV_N + DIM + h * HD;
        const float* vb = kb + DIM;

        // K transposed (d-major)
        #pragma unroll
        for (int i = tid; i < 2048; i += 256) {
            int r = i & 127;
            int dq = (i >> 7) * 4;
            float4 v = *(const float4*)(kb + (size_t)r * QKV_N + dq);
            sK[(dq + 0) * SQ_STRIDE + r] = v.x;
            sK[(dq + 1) * SQ_STRIDE + r] = v.y;
            sK[(dq + 2) * SQ_STRIDE + r] = v.z;
            sK[(dq + 3) * SQ_STRIDE + r] = v.w;
        }
        // V natural (k-major), coalesced
        #pragma unroll
        for (int i = tid; i < 2048; i += 256) {
            int r = i >> 4;
            int dq = (i & 15) * 4;
            *(float4*)(&sV[r * 64 + dq]) = *(const float4*)(vb + (size_t)r * QKV_N + dq);
        }
        __syncthreads();

        // ---- phase A: scores 8x8 per thread ----
        float acc[8][8];
        #pragma unroll
        for (int i = 0; i < 8; i++)
            #pragma unroll
            for (int j = 0; j < 8; j++) acc[i][j] = 0.f;

        #pragma unroll 4
        for (int d = 0; d < 64; d++) {
            float a[8], bk[8];
            #pragma unroll
            for (int i = 0; i < 8; i++) a[i] = sQ[d * SQ_STRIDE + ty * 8 + i];
            #pragma unroll
            for (int j = 0; j < 8; j++) bk[j] = sK[d * SQ_STRIDE + tk + 16 * j];
            #pragma unroll
            for (int i = 0; i < 8; i++)
                #pragma unroll
                for (int j = 0; j < 8; j++)
                    acc[i][j] += a[i] * bk[j];
        }

        // causal mask (diagonal tile only; s0 == qbase there)
        if (kt == ntiles - 1) {
            #pragma unroll
            for (int i = 0; i < 8; i++) {
                int ql = ty * 8 + i;
                #pragma unroll
                for (int j = 0; j < 8; j++)
                    if (tk + 16 * j > ql) acc[i][j] = -1e30f;
            }
        }

        // ---- softmax update ----
        #pragma unroll
        for (int i = 0; i < 8; i++) {
            const int row = ty * 8 + i;
            float mx = acc[i][0];
            #pragma unroll
            for (int j = 1; j < 8; j++) mx = fmaxf(mx, acc[i][j]);
            mx = fmaxf(mx, __shfl_xor_sync(0xffffffffu, mx, 1));
            mx = fmaxf(mx, __shfl_xor_sync(0xffffffffu, mx, 2));
            mx = fmaxf(mx, __shfl_xor_sync(0xffffffffu, mx, 4));
            mx = fmaxf(mx, __shfl_xor_sync(0xffffffffu, mx, 8));
            const float mold = sM[row];
            const float mnew = fmaxf(mold, mx);

            float sum = 0.f;
            #pragma unroll
            for (int j = 0; j < 8; j++) {
                float p = __expf(acc[i][j] - mnew);
                sum += p;
                sP[row * SP_STRIDE + tk + 16 * j] = p;
            }
            sum += __shfl_xor_sync(0xffffffffu, sum, 1);
            sum += __shfl_xor_sync(0xffffffffu, sum, 2);
            sum += __shfl_xor_sync(0xffffffffu, sum, 4);
            sum += __shfl_xor_sync(0xffffffffu, sum, 8);

            if (tk == 0) {
                const float corr = __expf(mold - mnew);
                sCorr[row] = corr;
                sL[row] = sL[row] * corr + sum;
                sM[row] = mnew;
            }
        }
        __syncthreads();

        // ---- phase B: O += P @ V ; rows ty*8+i, dims tk*4.. ----
        #pragma unroll
        for (int i = 0; i < 8; i++) {
            const float c = sCorr[ty * 8 + i];
            #pragma unroll
            for (int j = 0; j < 4; j++) o_acc[i][j] *= c;
        }

        #pragma unroll 2
        for (int k = 0; k < KTILE; k++) {
            float4 v = *(const float4*)(&sV[k * 64 + tk * 4]);
            #pragma unroll
            for (int i = 0; i < 8; i++) {
                float p = sP[(ty * 8 + i) * SP_STRIDE + k];
                o_acc[i][0] += p * v.x;
                o_acc[i][1] += p * v.y;
                o_acc[i][2] += p * v.z;
                o_acc[i][3] += p * v.w;
            }
        }
        __syncthreads();
    }

    // ---- epilogue ----
    #pragma unroll
    for (int i = 0; i < 8; i++) {
        const int row = ty * 8 + i;
        const float inv = 1.f / sL[row];
        float4 v;
        v.x = o_acc[i][0] * inv;
        v.y = o_acc[i][1] * inv;
        v.z = o_acc[i][2] * inv;
        v.w = o_acc[i][3] * inv;
        *(float4*)(att + ((size_t)(b * SEQ + qbase + row)) * DIM + h * HD + tk * 4) = v;
    }
}

// ---------------- launch ----------------
extern "C" void kernel_launch(void* const* d_in, const int* in_sizes, int n_in,
                              void* d_out, int out_size)
{
    const float* x     = (const float*)d_in[0];
    const float* Wqkv  = (const float*)d_in[1];
    const float* bqkv  = (const float*)d_in[2];
    const float* Wproj = (const float*)d_in[3];
    const float* bproj = (const float*)d_in[4];
    float* out = (float*)d_out;

    float* qkv = nullptr;
    float* att = nullptr;
    cudaGetSymbolAddress((void**)&qkv, g_qkv);
    cudaGetSymbolAddress((void**)&att, g_att);

    const size_t attn_smem = (size_t)SMEM_FLOATS * sizeof(float);
    static bool configured = false;
    if (!configured) {
        cudaFuncSetAttribute(attn_kernel, cudaFuncAttributeMaxDynamicSharedMemorySize,
                             (int)attn_smem);
        configured = true;
    }

    dim3 g1(QKV_N / BN, M_ROWS / BM);
    sgemm_bias<<<g1, 256>>>(x, Wqkv, bqkv, qkv, M_ROWS, QKV_N, DIM);

    dim3 g2(SEQ / QT, NH, BSZ);
    attn_kernel<<<g2, 256, attn_smem>>>(qkv, att);

    dim3 g3(DIM / BN, M_ROWS / BM);
    sgemm_bias<<<g3, 256>>>(att, Wproj, bproj, out, M_ROWS, DIM, DIM);
}